// round 3
// baseline (speedup 1.0000x reference)
#include <cuda_runtime.h>
#include <cuda_bf16.h>
#include <stdint.h>
#include <math.h>

typedef __nv_bfloat16 bf16;

#define S_LEN 128
#define BATCH 64
#define T_LEN 64
#define EMBD  256
#define HID   512
#define DHID  1024
#define VOC   32000

// ---------------------------------------------------------------------------
// Device scratch (no allocation allowed -> __device__ globals)
// ---------------------------------------------------------------------------
__device__ bf16  g_we0_ih[2][2048 * 256];
__device__ bf16  g_we0_hh[2][2048 * 512];
__device__ float g_be0[2][2048];
__device__ bf16  g_we1_ih[2][2048 * 1024];
__device__ bf16  g_we1_hh[2][2048 * 512];
__device__ float g_be1[2][2048];
__device__ bf16  g_wd0_ih[4096 * 256];
__device__ bf16  g_wd0_hh[4096 * 1024];
__device__ float g_bd0[4096];
__device__ bf16  g_wd1_ih[4096 * 1024];
__device__ bf16  g_wd1_hh[4096 * 1024];
__device__ float g_bd1[4096];
__device__ bf16  g_wout[(size_t)VOC * 1024];

__device__ bf16  g_xsrc[8192 * 256];     // embedded source  (S*B, E)
__device__ bf16  g_xdec[4096 * 256];     // embedded decoder input (T*B, E)
__device__ bf16  g_ya[8192 * 1024];      // enc layer0 output  [S*B][2H]
__device__ bf16  g_yda[4096 * 1024];     // dec layer0 output
__device__ bf16  g_ydb[4096 * 1024];     // dec layer1 output
__device__ float g_xw[2][8192 * 2048];   // gate input projections (per dir); dec uses [0] flat (4096*4096)
__device__ bf16  g_hbuf[2][2][64 * 1024];// [parity][dir]
__device__ float g_cbuf[2][64 * 1024];   // [dir]
__device__ bf16  g_dech0[2][64 * 1024];  // decoder init h per layer  [hf|hb]
__device__ float g_decc0[2][64 * 1024];  // decoder init c per layer

// ---------------------------------------------------------------------------
// Small helpers
// ---------------------------------------------------------------------------
__device__ __forceinline__ float sigf(float x) { return 1.f / (1.f + expf(-x)); }

__device__ __forceinline__ void mma16816(float* c, uint32_t a0, uint32_t a1, uint32_t a2, uint32_t a3,
                                         uint32_t b0, uint32_t b1) {
    asm volatile(
        "mma.sync.aligned.m16n8k16.row.col.f32.bf16.bf16.f32 "
        "{%0,%1,%2,%3},{%4,%5,%6,%7},{%8,%9},{%0,%1,%2,%3};"
        : "+f"(c[0]), "+f"(c[1]), "+f"(c[2]), "+f"(c[3])
        : "r"(a0), "r"(a1), "r"(a2), "r"(a3), "r"(b0), "r"(b1));
}

__device__ __forceinline__ void cp16(void* smem, const void* gmem) {
    uint32_t s = (uint32_t)__cvta_generic_to_shared(smem);
    asm volatile("cp.async.cg.shared.global [%0], [%1], 16;\n" ::"r"(s), "l"(gmem));
}
__device__ __forceinline__ void cp_commit() { asm volatile("cp.async.commit_group;\n"); }
template <int N>
__device__ __forceinline__ void cp_wait() { asm volatile("cp.async.wait_group %0;\n" ::"n"(N)); }

// ---------------------------------------------------------------------------
// Weight conversion / permutation kernels
// row r (gate = r/H, unit j = r%H)  ->  permuted row 4*j + gate
// ---------------------------------------------------------------------------
__global__ void conv_permute(const float* __restrict__ src, bf16* __restrict__ dst, int H, int K, int n) {
    for (int idx = blockIdx.x * blockDim.x + threadIdx.x; idx < n; idx += gridDim.x * blockDim.x) {
        int r = idx / K, k = idx - r * K;
        int gate = r / H, j = r - gate * H;
        dst[(size_t)(j * 4 + gate) * K + k] = __float2bfloat16(src[idx]);
    }
}
__global__ void conv_bias(const float* __restrict__ bih, const float* __restrict__ bhh,
                          float* __restrict__ dst, int H, int n) {
    for (int r = blockIdx.x * blockDim.x + threadIdx.x; r < n; r += gridDim.x * blockDim.x) {
        int gate = r / H, j = r - gate * H;
        dst[j * 4 + gate] = bih[r] + bhh[r];
    }
}
__global__ void conv_plain(const float* __restrict__ src, bf16* __restrict__ dst, size_t n) {
    for (size_t i = blockIdx.x * (size_t)blockDim.x + threadIdx.x; i < n; i += (size_t)gridDim.x * blockDim.x)
        dst[i] = __float2bfloat16(src[i]);
}

// ---------------------------------------------------------------------------
// Embedding gathers
// ---------------------------------------------------------------------------
__global__ void embed_src(const int* __restrict__ sent, const float* __restrict__ emb, bf16* __restrict__ x) {
    int idx = blockIdx.x * blockDim.x + threadIdx.x;  // 8192*256
    if (idx >= 8192 * 256) return;
    int row = idx >> 8, e = idx & 255;
    x[idx] = __float2bfloat16(emb[(size_t)sent[row] * EMBD + e]);
}
__global__ void embed_dec(const int* __restrict__ sent, const int* __restrict__ targ,
                          const float* __restrict__ emb, bf16* __restrict__ x) {
    int idx = blockIdx.x * blockDim.x + threadIdx.x;  // 4096*256
    if (idx >= 4096 * 256) return;
    int row = idx >> 8, e = idx & 255;
    int t = row >> 6, b = row & 63;
    int tok = (t == 0) ? sent[(S_LEN - 1) * BATCH + b] : targ[(t - 1) * BATCH + b];
    x[idx] = __float2bfloat16(emb[(size_t)tok * EMBD + e]);
}

// ---------------------------------------------------------------------------
// Big GEMM: C[M][N] f32 = A(bf16 MxK rowmaj) @ B(bf16 NxK rowmaj)^T + bias[N]
// tile 128x128x32, 256 threads, cp.async double buffered
// M % 128 == 0, N % 128 == 0, K % 32 == 0
// ---------------------------------------------------------------------------
#define GBM 128
#define GBK 32
#define GPAD 8
__global__ __launch_bounds__(256) void gemm_bias(const bf16* __restrict__ A, const bf16* __restrict__ B,
                                                 const float* __restrict__ bias, float* __restrict__ C,
                                                 int M, int N, int K) {
    __shared__ bf16 As[2][GBM][GBK + GPAD];
    __shared__ bf16 Bs[2][GBM][GBK + GPAD];
    int tid = threadIdx.x;
    int m0 = blockIdx.y * GBM, n0 = blockIdx.x * GBM;
    int warp = tid >> 5, lane = tid & 31, g = lane >> 2, tg = lane & 3;
    int wm = warp >> 1, wn = warp & 1;
    float acc[2][8][4];
#pragma unroll
    for (int a = 0; a < 2; a++)
#pragma unroll
        for (int b = 0; b < 8; b++)
#pragma unroll
            for (int c = 0; c < 4; c++) acc[a][b][c] = 0.f;

    int lrow = tid >> 2, lq = tid & 3;  // 64 rows x 4 quads
    int KT = K / GBK;

    {
        const bf16* Ap = A + (size_t)(m0 + lrow) * K + lq * 8;
        const bf16* Bp = B + (size_t)(n0 + lrow) * K + lq * 8;
        cp16(&As[0][lrow][lq * 8], Ap);
        cp16(&As[0][lrow + 64][lq * 8], Ap + (size_t)64 * K);
        cp16(&Bs[0][lrow][lq * 8], Bp);
        cp16(&Bs[0][lrow + 64][lq * 8], Bp + (size_t)64 * K);
        cp_commit();
    }
    for (int kt = 0; kt < KT; kt++) {
        int cur = kt & 1;
        if (kt + 1 < KT) {
            int k0 = (kt + 1) * GBK;
            const bf16* Ap = A + (size_t)(m0 + lrow) * K + k0 + lq * 8;
            const bf16* Bp = B + (size_t)(n0 + lrow) * K + k0 + lq * 8;
            cp16(&As[cur ^ 1][lrow][lq * 8], Ap);
            cp16(&As[cur ^ 1][lrow + 64][lq * 8], Ap + (size_t)64 * K);
            cp16(&Bs[cur ^ 1][lrow][lq * 8], Bp);
            cp16(&Bs[cur ^ 1][lrow + 64][lq * 8], Bp + (size_t)64 * K);
            cp_commit();
            cp_wait<1>();
        } else {
            cp_wait<0>();
        }
        __syncthreads();
#pragma unroll
        for (int kk = 0; kk < 2; kk++) {
            uint32_t afr[2][4];
#pragma unroll
            for (int mi = 0; mi < 2; mi++) {
                int r = wm * 32 + mi * 16;
                afr[mi][0] = *(uint32_t*)&As[cur][r + g][kk * 16 + tg * 2];
                afr[mi][1] = *(uint32_t*)&As[cur][r + g + 8][kk * 16 + tg * 2];
                afr[mi][2] = *(uint32_t*)&As[cur][r + g][kk * 16 + tg * 2 + 8];
                afr[mi][3] = *(uint32_t*)&As[cur][r + g + 8][kk * 16 + tg * 2 + 8];
            }
#pragma unroll
            for (int ni = 0; ni < 8; ni++) {
                int cb = wn * 64 + ni * 8;
                uint32_t b0 = *(uint32_t*)&Bs[cur][cb + g][kk * 16 + tg * 2];
                uint32_t b1 = *(uint32_t*)&Bs[cur][cb + g][kk * 16 + tg * 2 + 8];
                mma16816(acc[0][ni], afr[0][0], afr[0][1], afr[0][2], afr[0][3], b0, b1);
                mma16816(acc[1][ni], afr[1][0], afr[1][1], afr[1][2], afr[1][3], b0, b1);
            }
        }
        __syncthreads();
    }
    // epilogue: + bias, f32 out
#pragma unroll
    for (int mi = 0; mi < 2; mi++) {
#pragma unroll
        for (int ni = 0; ni < 8; ni++) {
            int r = m0 + wm * 32 + mi * 16 + g;
            int c = n0 + wn * 64 + ni * 8 + tg * 2;
            float bv0 = bias[c], bv1 = bias[c + 1];
            float2 v0 = make_float2(acc[mi][ni][0] + bv0, acc[mi][ni][1] + bv1);
            float2 v1 = make_float2(acc[mi][ni][2] + bv0, acc[mi][ni][3] + bv1);
            *(float2*)&C[(size_t)r * N + c] = v0;
            *(float2*)&C[(size_t)(r + 8) * N + c] = v1;
        }
    }
}

// ---------------------------------------------------------------------------
// Fused LSTM step: gates = xw[t] + h_prev @ Whh^T  (Whh gate-interleaved),
// cell nonlinearity in epilogue. Block = 64 batch rows x 64 gate-cols.
// grid = (N/64, 1, ndirs), block = 128 threads. cp.async double-buffered.
// ---------------------------------------------------------------------------
struct StepArgs {
    const float* xw[2];
    const bf16* hprev[2];
    bf16* hnew[2];
    const float* cin[2];
    float* cout[2];
    const bf16* Whh[2];
    bf16* y;
    int y_stride;
    int y_off[2];
    int t[2];
    int K;  // hidden dim of h (512 or 1024)
    int N;  // 4*H (2048 or 4096)
    bf16* exp_h;
    float* exp_c;
    int exp_off[2];
    int exp_dim;
    int do_export;
};

__global__ __launch_bounds__(128) void lstm_step(StepArgs p) {
    __shared__ bf16 As[2][64][GBK + GPAD];
    __shared__ bf16 Bs[2][64][GBK + GPAD];
    int dir = blockIdx.z;
    int tid = threadIdx.x, warp = tid >> 5, lane = tid & 31, g = lane >> 2, tg = lane & 3;
    int nb = blockIdx.x * 64;
    int N = p.N, K = p.K;
    float acc[8][4];
#pragma unroll
    for (int a = 0; a < 8; a++)
#pragma unroll
        for (int b = 0; b < 4; b++) acc[a][b] = 0.f;

    const bf16* hp = p.hprev[dir];
    if (hp) {
        const bf16* W = p.Whh[dir] + (size_t)nb * K;
        int lr = tid >> 2, lq = tid & 3;  // 32 rows x 4 quads per pass, 2 passes
        int KT = K / GBK;
        {
            const bf16* Ap = hp + (size_t)lr * K + lq * 8;
            const bf16* Bp = W + (size_t)lr * K + lq * 8;
            cp16(&As[0][lr][lq * 8], Ap);
            cp16(&As[0][lr + 32][lq * 8], Ap + (size_t)32 * K);
            cp16(&Bs[0][lr][lq * 8], Bp);
            cp16(&Bs[0][lr + 32][lq * 8], Bp + (size_t)32 * K);
            cp_commit();
        }
        for (int kt = 0; kt < KT; kt++) {
            int cur = kt & 1;
            if (kt + 1 < KT) {
                int k0 = (kt + 1) * GBK;
                const bf16* Ap = hp + (size_t)lr * K + k0 + lq * 8;
                const bf16* Bp = W + (size_t)lr * K + k0 + lq * 8;
                cp16(&As[cur ^ 1][lr][lq * 8], Ap);
                cp16(&As[cur ^ 1][lr + 32][lq * 8], Ap + (size_t)32 * K);
                cp16(&Bs[cur ^ 1][lr][lq * 8], Bp);
                cp16(&Bs[cur ^ 1][lr + 32][lq * 8], Bp + (size_t)32 * K);
                cp_commit();
                cp_wait<1>();
            } else {
                cp_wait<0>();
            }
            __syncthreads();
#pragma unroll
            for (int kk = 0; kk < 2; kk++) {
                int r = warp * 16;
                uint32_t a0 = *(uint32_t*)&As[cur][r + g][kk * 16 + tg * 2];
                uint32_t a1 = *(uint32_t*)&As[cur][r + g + 8][kk * 16 + tg * 2];
                uint32_t a2 = *(uint32_t*)&As[cur][r + g][kk * 16 + tg * 2 + 8];
                uint32_t a3 = *(uint32_t*)&As[cur][r + g + 8][kk * 16 + tg * 2 + 8];
#pragma unroll
                for (int ni = 0; ni < 8; ni++) {
                    uint32_t b0 = *(uint32_t*)&Bs[cur][ni * 8 + g][kk * 16 + tg * 2];
                    uint32_t b1 = *(uint32_t*)&Bs[cur][ni * 8 + g][kk * 16 + tg * 2 + 8];
                    mma16816(acc[ni], a0, a1, a2, a3, b0, b1);
                }
            }
            __syncthreads();
        }
    }
    // add precomputed input projection (+ folded biases)
    const float* xw = p.xw[dir] + (size_t)p.t[dir] * 64 * N;
    int r0 = warp * 16 + g;
#pragma unroll
    for (int ni = 0; ni < 8; ni++) {
        int c = nb + ni * 8 + tg * 2;
        float2 x0 = *(const float2*)&xw[(size_t)r0 * N + c];
        float2 x1 = *(const float2*)&xw[(size_t)(r0 + 8) * N + c];
        acc[ni][0] += x0.x;
        acc[ni][1] += x0.y;
        acc[ni][2] += x1.x;
        acc[ni][3] += x1.y;
    }
    // LSTM cell. cols: 4j..4j+3 = (i,f,g,o); lane pairs (tg, tg^1) share a unit.
    int hd = N >> 2;
#pragma unroll
    for (int ni = 0; ni < 8; ni++) {
#pragma unroll
        for (int h2 = 0; h2 < 2; h2++) {
            float v0 = acc[ni][2 * h2], v1 = acc[ni][2 * h2 + 1];
            float w0 = __shfl_xor_sync(0xffffffffu, v0, 1);
            float w1 = __shfl_xor_sync(0xffffffffu, v1, 1);
            if ((tg & 1) == 0) {
                float iv = v0, fv = v1, gv = w0, ov = w1;
                int j = blockIdx.x * 16 + ni * 2 + (tg >> 1);
                int b = warp * 16 + g + h2 * 8;
                size_t ci = (size_t)b * hd + j;
                float cold = p.cin[dir] ? p.cin[dir][ci] : 0.f;
                float cn = sigf(fv) * cold + sigf(iv) * tanhf(gv);
                float hn = sigf(ov) * tanhf(cn);
                p.cout[dir][ci] = cn;
                p.hnew[dir][ci] = __float2bfloat16(hn);
                if (p.y)
                    p.y[(size_t)(p.t[dir] * 64 + b) * p.y_stride + p.y_off[dir] + j] = __float2bfloat16(hn);
                if (p.do_export) {
                    size_t ei = (size_t)b * p.exp_dim + p.exp_off[dir] + j;
                    p.exp_h[ei] = __float2bfloat16(hn);
                    p.exp_c[ei] = cn;
                }
            }
        }
    }
}

// ---------------------------------------------------------------------------
// In-place log_softmax over rows of 32000 f32 (online max/sum: 2 passes)
// ---------------------------------------------------------------------------
__global__ void logsoftmax_kernel(float* __restrict__ out) {
    float* x = out + (size_t)blockIdx.x * VOC;
    __shared__ float redm[256];
    __shared__ float reds[256];
    int tid = threadIdx.x;
    const float4* x4 = (const float4*)x;
    float m = -1e30f, ssum = 0.f;
    for (int i = tid; i < VOC / 4; i += 256) {
        float4 v = x4[i];
        float vm = fmaxf(fmaxf(v.x, v.y), fmaxf(v.z, v.w));
        if (vm > m) {
            ssum = ssum * expf(m - vm);
            m = vm;
        }
        ssum += expf(v.x - m) + expf(v.y - m) + expf(v.z - m) + expf(v.w - m);
    }
    redm[tid] = m;
    reds[tid] = ssum;
    __syncthreads();
    for (int s = 128; s > 0; s >>= 1) {
        if (tid < s) {
            float m2 = redm[tid + s], s2 = reds[tid + s];
            float m1 = redm[tid], s1 = reds[tid];
            float M = fmaxf(m1, m2);
            redm[tid] = M;
            reds[tid] = s1 * expf(m1 - M) + s2 * expf(m2 - M);
        }
        __syncthreads();
    }
    float lse = redm[0] + logf(reds[0]);
    __syncthreads();
    float4* xw4 = (float4*)x;
    for (int i = tid; i < VOC / 4; i += 256) {
        float4 v = xw4[i];
        v.x -= lse; v.y -= lse; v.z -= lse; v.w -= lse;
        xw4[i] = v;
    }
}

// ---------------------------------------------------------------------------
// Host
// ---------------------------------------------------------------------------
static void* symaddr(const void* sym) {
    void* p = nullptr;
    cudaGetSymbolAddress(&p, sym);
    return p;
}

extern "C" void kernel_launch(void* const* d_in, const int* in_sizes, int n_in,
                              void* d_out, int out_size) {
    cudaStream_t s = 0;
    const int* sent = (const int*)d_in[0];
    const int* targ = (const int*)d_in[1];
    const float* emb = (const float*)d_in[2];
    const float* e0_Wih = (const float*)d_in[3];
    const float* e0_Whh = (const float*)d_in[4];
    const float* e0_bih = (const float*)d_in[5];
    const float* e0_bhh = (const float*)d_in[6];
    const float* e1_Wih = (const float*)d_in[7];
    const float* e1_Whh = (const float*)d_in[8];
    const float* e1_bih = (const float*)d_in[9];
    const float* e1_bhh = (const float*)d_in[10];
    const float* d0_Wih = (const float*)d_in[11];
    const float* d0_Whh = (const float*)d_in[12];
    const float* d0_bih = (const float*)d_in[13];
    const float* d0_bhh = (const float*)d_in[14];
    const float* d1_Wih = (const float*)d_in[15];
    const float* d1_Whh = (const float*)d_in[16];
    const float* d1_bih = (const float*)d_in[17];
    const float* d1_bhh = (const float*)d_in[18];
    const float* W_out = (const float*)d_in[19];
    const float* b_out = (const float*)d_in[20];

    bf16* we0_ih = (bf16*)symaddr(g_we0_ih);
    bf16* we0_hh = (bf16*)symaddr(g_we0_hh);
    float* be0 = (float*)symaddr(g_be0);
    bf16* we1_ih = (bf16*)symaddr(g_we1_ih);
    bf16* we1_hh = (bf16*)symaddr(g_we1_hh);
    float* be1 = (float*)symaddr(g_be1);
    bf16* wd0_ih = (bf16*)symaddr(g_wd0_ih);
    bf16* wd0_hh = (bf16*)symaddr(g_wd0_hh);
    float* bd0 = (float*)symaddr(g_bd0);
    bf16* wd1_ih = (bf16*)symaddr(g_wd1_ih);
    bf16* wd1_hh = (bf16*)symaddr(g_wd1_hh);
    float* bd1 = (float*)symaddr(g_bd1);
    bf16* wout = (bf16*)symaddr(g_wout);
    bf16* xsrc = (bf16*)symaddr(g_xsrc);
    bf16* xdec = (bf16*)symaddr(g_xdec);
    bf16* ya = (bf16*)symaddr(g_ya);
    bf16* yda = (bf16*)symaddr(g_yda);
    bf16* ydb = (bf16*)symaddr(g_ydb);
    float* xwb = (float*)symaddr(g_xw);
    bf16* hbuf = (bf16*)symaddr(g_hbuf);
    float* cbuf = (float*)symaddr(g_cbuf);
    bf16* dech0 = (bf16*)symaddr(g_dech0);
    float* decc0 = (float*)symaddr(g_decc0);

    const size_t XW_STRIDE = (size_t)8192 * 2048;  // per-dir xw buffer
    const size_t HB = (size_t)64 * 1024;           // per h/c buffer
    float* xw0 = xwb;
    float* xw1 = xwb + XW_STRIDE;

    // ---- weight conversion + gate permutation ----
    auto cvtW = [&](const float* src, bf16* dst, int H, int K) {
        int n = 4 * H * K;
        conv_permute<<<(n + 255) / 256, 256, 0, s>>>(src, dst, H, K, n);
    };
    auto cvtB = [&](const float* bih, const float* bhh, float* dst, int H) {
        int n = 4 * H;
        conv_bias<<<(n + 255) / 256, 256, 0, s>>>(bih, bhh, dst, H, n);
    };
    for (int d = 0; d < 2; d++) {
        cvtW(e0_Wih + (size_t)d * 2048 * 256, we0_ih + (size_t)d * 2048 * 256, HID, 256);
        cvtW(e0_Whh + (size_t)d * 2048 * 512, we0_hh + (size_t)d * 2048 * 512, HID, 512);
        cvtB(e0_bih + d * 2048, e0_bhh + d * 2048, be0 + d * 2048, HID);
        cvtW(e1_Wih + (size_t)d * 2048 * 1024, we1_ih + (size_t)d * 2048 * 1024, HID, 1024);
        cvtW(e1_Whh + (size_t)d * 2048 * 512, we1_hh + (size_t)d * 2048 * 512, HID, 512);
        cvtB(e1_bih + d * 2048, e1_bhh + d * 2048, be1 + d * 2048, HID);
    }
    cvtW(d0_Wih, wd0_ih, DHID, 256);
    cvtW(d0_Whh, wd0_hh, DHID, 1024);
    cvtB(d0_bih, d0_bhh, bd0, DHID);
    cvtW(d1_Wih, wd1_ih, DHID, 1024);
    cvtW(d1_Whh, wd1_hh, DHID, 1024);
    cvtB(d1_bih, d1_bhh, bd1, DHID);
    {
        size_t n = (size_t)VOC * 1024;
        conv_plain<<<(int)((n + 255) / 256), 256, 0, s>>>(W_out, wout, n);
    }

    // ---- embeddings ----
    embed_src<<<(8192 * 256 + 255) / 256, 256, 0, s>>>(sent, emb, xsrc);
    embed_dec<<<(4096 * 256 + 255) / 256, 256, 0, s>>>(sent, targ, emb, xdec);

    auto gemm = [&](const bf16* A, const bf16* B, const float* bias, float* C, int M, int N, int K) {
        dim3 gr(N / 128, M / 128);
        gemm_bias<<<gr, 256, 0, s>>>(A, B, bias, C, M, N, K);
    };

    // ---- encoder layers ----
    auto enc_layer = [&](const bf16* Whh_base, bf16* yout, bf16* exph, float* expc) {
        for (int i = 0; i < S_LEN; i++) {
            StepArgs a = {};
            a.N = 2048;
            a.K = HID;
            a.xw[0] = xw0;
            a.xw[1] = xw1;
            a.Whh[0] = Whh_base;
            a.Whh[1] = Whh_base + (size_t)2048 * 512;
            a.t[0] = i;
            a.t[1] = S_LEN - 1 - i;
            int pi = i & 1, po = pi ^ 1;
            for (int d = 0; d < 2; d++) {
                a.hprev[d] = i ? hbuf + ((size_t)pi * 2 + d) * HB : nullptr;
                a.hnew[d] = hbuf + ((size_t)po * 2 + d) * HB;
                a.cin[d] = i ? cbuf + (size_t)d * HB : nullptr;
                a.cout[d] = cbuf + (size_t)d * HB;
            }
            a.y = yout;
            a.y_stride = 1024;
            a.y_off[0] = 0;
            a.y_off[1] = 512;
            a.do_export = (i == S_LEN - 1);
            a.exp_h = exph;
            a.exp_c = expc;
            a.exp_off[0] = 0;
            a.exp_off[1] = 512;
            a.exp_dim = 1024;
            lstm_step<<<dim3(2048 / 64, 1, 2), 128, 0, s>>>(a);
        }
    };
    auto dec_layer = [&](const bf16* Whh, const bf16* h0, const float* c0, bf16* yout) {
        for (int i = 0; i < T_LEN; i++) {
            StepArgs a = {};
            a.N = 4096;
            a.K = DHID;
            a.xw[0] = xw0;
            a.Whh[0] = Whh;
            a.t[0] = i;
            int pi = i & 1, po = pi ^ 1;
            a.hprev[0] = i ? hbuf + (size_t)pi * 2 * HB : h0;
            a.hnew[0] = hbuf + (size_t)po * 2 * HB;
            a.cin[0] = i ? cbuf : c0;
            a.cout[0] = cbuf;
            a.y = yout;
            a.y_stride = 1024;
            a.y_off[0] = 0;
            lstm_step<<<dim3(4096 / 64, 1, 1), 128, 0, s>>>(a);
        }
    };

    // encoder layer 0
    for (int d = 0; d < 2; d++)
        gemm(xsrc, we0_ih + (size_t)d * 2048 * 256, be0 + d * 2048, (d ? xw1 : xw0), 8192, 2048, 256);
    enc_layer(we0_hh, ya, dech0, decc0);
    // encoder layer 1 (ys not needed)
    for (int d = 0; d < 2; d++)
        gemm(ya, we1_ih + (size_t)d * 2048 * 1024, be1 + d * 2048, (d ? xw1 : xw0), 8192, 2048, 1024);
    enc_layer(we1_hh, nullptr, dech0 + HB, decc0 + HB);
    // decoder layer 0
    gemm(xdec, wd0_ih, bd0, xw0, 4096, 4096, 256);
    dec_layer(wd0_hh, dech0, decc0, yda);
    // decoder layer 1
    gemm(yda, wd1_ih, bd1, xw0, 4096, 4096, 1024);
    dec_layer(wd1_hh, dech0 + HB, decc0 + HB, ydb);

    // output projection + log_softmax
    gemm(ydb, wout, b_out, (float*)d_out, 4096, VOC, 1024);
    logsoftmax_kernel<<<4096, 256, 0, s>>>((float*)d_out);
}